// round 16
// baseline (speedup 1.0000x reference)
#include <cuda_runtime.h>
#include <cuda_fp16.h>
#include <math.h>

// HashedInterpolator: 3-D hash-grid trilinear interpolation.
// position: [B,3] f32;  hash_table: [524288,4] f32;  out: [B,4] f32.
//
// R16 (final polish): R15 + uniform full-block fast path (batch = 2^21 =
// 4096 * PPB exactly -> guards dead in the hot path) + streaming hints on
// the read-once position / prepass streams so the 4MB fp16 shadow table
// stays L2-resident.
// Converged design: lane-pair x-merge (dim-x hash prime = 1 => corner rows
// {h, h^1} adjacent), fp16 shadow table (8B rows), 4 points/thread (MLP=16),
// __ldg gathers, prepass 2 rows/thread + STG.128.
// Floor: ~4.25 distinct 128B lines/pt x ~2.07 cyc L1TEX divergent replay.

#define HG_ENTRIES 524288
#define HG_MASK    (HG_ENTRIES - 1)
#define HG_P1      19349663u
#define HG_P2      83492791u

#define TPB  256
#define HALF 128               // point-slots per quarter (2 lanes per point)
#define PPB  512               // 4 points per lane-pair per block

__device__ __align__(16) static __half g_tbl16[HG_ENTRIES * 4];   // 4 MB

__global__ __launch_bounds__(256) void convert_table_kernel(
    const float4* __restrict__ table)
{
    int i = blockIdx.x * blockDim.x + threadIdx.x;   // 2 rows per thread
    int r = 2 * i;
    if (r < HG_ENTRIES) {
        float4 v0 = __ldcs(&table[r]);       // read-once stream
        float4 v1 = __ldcs(&table[r + 1]);
        uint4 packed;
        __half2 h;
        h = __floats2half2_rn(v0.x, v0.y);  packed.x = *(unsigned*)&h;
        h = __floats2half2_rn(v0.z, v0.w);  packed.y = *(unsigned*)&h;
        h = __floats2half2_rn(v1.x, v1.y);  packed.z = *(unsigned*)&h;
        h = __floats2half2_rn(v1.z, v1.w);  packed.w = *(unsigned*)&h;
        *(uint4*)(g_tbl16 + 4 * r) = packed;
    }
}

__device__ __forceinline__ void hash4(const float* sp, int slot, int xbit,
                                      unsigned& h00, unsigned& h01,
                                      unsigned& h10, unsigned& h11)
{
    float px = sp[3 * slot + 0];
    float py = sp[3 * slot + 1];
    float pz = sp[3 * slot + 2];
    unsigned hx  = (unsigned)((int)floorf(px * 512.0f) + xbit);
    unsigned hy0 = (unsigned)((int)floorf(py * 512.0f)) * HG_P1;
    unsigned hz0 = (unsigned)((int)floorf(pz * 512.0f)) * HG_P2;
    unsigned hy1 = hy0 + HG_P1;    // (ly+1)*P1 — arithmetic add
    unsigned hz1 = hz0 + HG_P2;    // (lz+1)*P2
    h00 = (hx ^ hy0 ^ hz0) & HG_MASK;
    h01 = (hx ^ hy0 ^ hz1) & HG_MASK;
    h10 = (hx ^ hy1 ^ hz0) & HG_MASK;
    h11 = (hx ^ hy1 ^ hz1) & HG_MASK;
}

__device__ __forceinline__ float4 interp_point(const float* sp, int slot, int xbit,
                                               uint2 r00, uint2 r01,
                                               uint2 r10, uint2 r11)
{
    const float inv = 1.0f / 512.0f;   // exact; /size == *512 exactly
    float px = sp[3 * slot + 0];
    float py = sp[3 * slot + 1];
    float pz = sp[3 * slot + 2];
    int lx = (int)floorf(px * 512.0f);
    int ly = (int)floorf(py * 512.0f);
    int lz = (int)floorf(pz * 512.0f);
    float wx0 = (px - (float)lx * inv) * 512.0f;
    float wx1 = ((float)(lx + 1) * inv - px) * 512.0f;
    float wy0 = (py - (float)ly * inv) * 512.0f;
    float wy1 = ((float)(ly + 1) * inv - py) * 512.0f;
    float wz0 = (pz - (float)lz * inv) * 512.0f;
    float wz1 = ((float)(lz + 1) * inv - pz) * 512.0f;
    float wx = xbit ? wx1 : wx0;

    float w00 = wx * wy0 * wz0;
    float w01 = wx * wy0 * wz1;
    float w10 = wx * wy1 * wz0;
    float w11 = wx * wy1 * wz1;

    float4 acc;
    {
        float2 f0 = __half22float2(*(__half2*)&r00.x);
        float2 f1 = __half22float2(*(__half2*)&r00.y);
        acc.x = f0.x * w00;  acc.y = f0.y * w00;
        acc.z = f1.x * w00;  acc.w = f1.y * w00;
    }
    {
        float2 f0 = __half22float2(*(__half2*)&r01.x);
        float2 f1 = __half22float2(*(__half2*)&r01.y);
        acc.x = fmaf(f0.x, w01, acc.x);  acc.y = fmaf(f0.y, w01, acc.y);
        acc.z = fmaf(f1.x, w01, acc.z);  acc.w = fmaf(f1.y, w01, acc.w);
    }
    {
        float2 f0 = __half22float2(*(__half2*)&r10.x);
        float2 f1 = __half22float2(*(__half2*)&r10.y);
        acc.x = fmaf(f0.x, w10, acc.x);  acc.y = fmaf(f0.y, w10, acc.y);
        acc.z = fmaf(f1.x, w10, acc.z);  acc.w = fmaf(f1.y, w10, acc.w);
    }
    {
        float2 f0 = __half22float2(*(__half2*)&r11.x);
        float2 f1 = __half22float2(*(__half2*)&r11.y);
        acc.x = fmaf(f0.x, w11, acc.x);  acc.y = fmaf(f0.y, w11, acc.y);
        acc.z = fmaf(f1.x, w11, acc.z);  acc.w = fmaf(f1.y, w11, acc.w);
    }

    // Pair reduction: lane 2i += lane 2i+1.
    acc.x += __shfl_xor_sync(0xffffffffu, acc.x, 1);
    acc.y += __shfl_xor_sync(0xffffffffu, acc.y, 1);
    acc.z += __shfl_xor_sync(0xffffffffu, acc.z, 1);
    acc.w += __shfl_xor_sync(0xffffffffu, acc.w, 1);
    return acc;
}

__global__ __launch_bounds__(TPB, 4) void hashed_interp_kernel(
    const float* __restrict__ pos,
    float4* __restrict__ out,
    int batch)
{
    __shared__ float sp[3 * PPB];

    int t = threadIdx.x;
    int base = blockIdx.x * PPB;
    bool full = (base + PPB) <= batch;    // uniform per block

    // Stage this block's positions (3*512 floats = 384 float4s) coalesced.
    if (full) {
        const float4* src = (const float4*)(pos + 3 * base);  // 6144B-aligned
        #pragma unroll
        for (int k = 0; k < 384 / TPB * TPB; ) { k = 384; }    // (loop below)
        for (int v = t; v < 3 * PPB / 4; v += TPB)
            ((float4*)sp)[v] = __ldcs(&src[v]);
    } else {
        int nfloats = 3 * (batch - base);
        if (nfloats < 0) nfloats = 0;
        if (nfloats > 3 * PPB) nfloats = 3 * PPB;
        const float4* src = (const float4*)(pos + 3 * base);
        int nvec = nfloats >> 2;
        for (int v = t; v < nvec; v += TPB) ((float4*)sp)[v] = src[v];
        int rem = nfloats & 3;
        if (t < rem) sp[(nvec << 2) + t] = pos[3 * base + (nvec << 2) + t];
    }
    __syncthreads();

    int slot = t >> 1;          // 0..127
    int xbit = t & 1;
    int iA = base + slot;
    int iB = iA + HALF;
    int iC = iB + HALF;
    int iD = iC + HALF;
    bool hasA = full || (iA < batch);
    bool hasB = full || (iB < batch);
    bool hasC = full || (iC < batch);
    bool hasD = full || (iD < batch);

    const uint2* tb2 = (const uint2*)g_tbl16;   // one uint2 = one 8B row

    uint2 rA00, rA01, rA10, rA11;
    uint2 rB00, rB01, rB10, rB11;
    uint2 rC00, rC01, rC10, rC11;
    uint2 rD00, rD01, rD10, rD11;

    // Phase the hash computation so only 4 index regs are live at a time;
    // all 16 loads end up in flight before any weight math.
    {
        unsigned h0, h1, h2, h3;
        hash4(sp, slot, xbit, h0, h1, h2, h3);
        if (hasA) {
            rA00 = __ldg(&tb2[h0]);
            rA01 = __ldg(&tb2[h1]);
            rA10 = __ldg(&tb2[h2]);
            rA11 = __ldg(&tb2[h3]);
        }
    }
    {
        unsigned h0, h1, h2, h3;
        hash4(sp, slot + HALF, xbit, h0, h1, h2, h3);
        if (hasB) {
            rB00 = __ldg(&tb2[h0]);
            rB01 = __ldg(&tb2[h1]);
            rB10 = __ldg(&tb2[h2]);
            rB11 = __ldg(&tb2[h3]);
        }
    }
    {
        unsigned h0, h1, h2, h3;
        hash4(sp, slot + 2 * HALF, xbit, h0, h1, h2, h3);
        if (hasC) {
            rC00 = __ldg(&tb2[h0]);
            rC01 = __ldg(&tb2[h1]);
            rC10 = __ldg(&tb2[h2]);
            rC11 = __ldg(&tb2[h3]);
        }
    }
    {
        unsigned h0, h1, h2, h3;
        hash4(sp, slot + 3 * HALF, xbit, h0, h1, h2, h3);
        if (hasD) {
            rD00 = __ldg(&tb2[h0]);
            rD01 = __ldg(&tb2[h1]);
            rD10 = __ldg(&tb2[h2]);
            rD11 = __ldg(&tb2[h3]);
        }
    }

    if (hasA) {
        float4 acc = interp_point(sp, slot, xbit, rA00, rA01, rA10, rA11);
        if (xbit == 0) __stcs(&out[iA], acc);
    }
    if (hasB) {
        float4 acc = interp_point(sp, slot + HALF, xbit, rB00, rB01, rB10, rB11);
        if (xbit == 0) __stcs(&out[iB], acc);
    }
    if (hasC) {
        float4 acc = interp_point(sp, slot + 2 * HALF, xbit, rC00, rC01, rC10, rC11);
        if (xbit == 0) __stcs(&out[iC], acc);
    }
    if (hasD) {
        float4 acc = interp_point(sp, slot + 3 * HALF, xbit, rD00, rD01, rD10, rD11);
        if (xbit == 0) __stcs(&out[iD], acc);
    }
}

extern "C" void kernel_launch(void* const* d_in, const int* in_sizes, int n_in,
                              void* d_out, int out_size)
{
    const float* pos = (const float*)d_in[0];
    const float4* table = (const float4*)d_in[1];
    float4* out = (float4*)d_out;
    int batch = in_sizes[0] / 3;

    // Prepass: f32 table -> fp16 shadow (4MB), 2 rows/thread, STG.128.
    convert_table_kernel<<<(HG_ENTRIES / 2 + 255) / 256, 256>>>(table);

    int blocks = (batch + PPB - 1) / PPB;
    hashed_interp_kernel<<<blocks, TPB>>>(pos, out, batch);
}

// round 17
// speedup vs baseline: 1.0442x; 1.0442x over previous
#include <cuda_runtime.h>
#include <cuda_fp16.h>
#include <math.h>

// HashedInterpolator: 3-D hash-grid trilinear interpolation.
// position: [B,3] f32;  hash_table: [524288,4] f32;  out: [B,4] f32.
//
// FINAL (== R15, best measured: 47.1us total, 46.4us main kernel).
// Design: lane-pair x-merge (dim-x hash prime = 1 => corner rows {h, h^1}
// adjacent -> one L1 wavefront per yz-combo for even lx), fp16 shadow table
// (8B rows, 4MB, one-time prepass), 4 points/thread (MLP=16 gathers/lane),
// __ldg gathers, __stcs output.
// At the L1TEX divergent-replay floor: ~4.25 distinct 128B lines/point x
// ~2.07 cyc/line ~= 46us. All other variants measured 47-70us.

#define HG_ENTRIES 524288
#define HG_MASK    (HG_ENTRIES - 1)
#define HG_P1      19349663u
#define HG_P2      83492791u

#define TPB  256
#define HALF 128               // point-slots per quarter (2 lanes per point)
#define PPB  512               // 4 points per lane-pair per block

__device__ __align__(16) static __half g_tbl16[HG_ENTRIES * 4];   // 4 MB

__global__ __launch_bounds__(256) void convert_table_kernel(
    const float4* __restrict__ table)
{
    int i = blockIdx.x * blockDim.x + threadIdx.x;   // 2 rows per thread
    int r = 2 * i;
    if (r < HG_ENTRIES) {
        float4 v0 = table[r];
        float4 v1 = table[r + 1];
        uint4 packed;
        __half2 h;
        h = __floats2half2_rn(v0.x, v0.y);  packed.x = *(unsigned*)&h;
        h = __floats2half2_rn(v0.z, v0.w);  packed.y = *(unsigned*)&h;
        h = __floats2half2_rn(v1.x, v1.y);  packed.z = *(unsigned*)&h;
        h = __floats2half2_rn(v1.z, v1.w);  packed.w = *(unsigned*)&h;
        *(uint4*)(g_tbl16 + 4 * r) = packed;
    }
}

__device__ __forceinline__ void hash4(const float* sp, int slot, int xbit,
                                      unsigned& h00, unsigned& h01,
                                      unsigned& h10, unsigned& h11)
{
    float px = sp[3 * slot + 0];
    float py = sp[3 * slot + 1];
    float pz = sp[3 * slot + 2];
    unsigned hx  = (unsigned)((int)floorf(px * 512.0f) + xbit);
    unsigned hy0 = (unsigned)((int)floorf(py * 512.0f)) * HG_P1;
    unsigned hz0 = (unsigned)((int)floorf(pz * 512.0f)) * HG_P2;
    unsigned hy1 = hy0 + HG_P1;    // (ly+1)*P1 — arithmetic add
    unsigned hz1 = hz0 + HG_P2;    // (lz+1)*P2
    h00 = (hx ^ hy0 ^ hz0) & HG_MASK;
    h01 = (hx ^ hy0 ^ hz1) & HG_MASK;
    h10 = (hx ^ hy1 ^ hz0) & HG_MASK;
    h11 = (hx ^ hy1 ^ hz1) & HG_MASK;
}

__device__ __forceinline__ float4 interp_point(const float* sp, int slot, int xbit,
                                               uint2 r00, uint2 r01,
                                               uint2 r10, uint2 r11)
{
    const float inv = 1.0f / 512.0f;   // exact; /size == *512 exactly
    float px = sp[3 * slot + 0];
    float py = sp[3 * slot + 1];
    float pz = sp[3 * slot + 2];
    int lx = (int)floorf(px * 512.0f);
    int ly = (int)floorf(py * 512.0f);
    int lz = (int)floorf(pz * 512.0f);
    float wx0 = (px - (float)lx * inv) * 512.0f;
    float wx1 = ((float)(lx + 1) * inv - px) * 512.0f;
    float wy0 = (py - (float)ly * inv) * 512.0f;
    float wy1 = ((float)(ly + 1) * inv - py) * 512.0f;
    float wz0 = (pz - (float)lz * inv) * 512.0f;
    float wz1 = ((float)(lz + 1) * inv - pz) * 512.0f;
    float wx = xbit ? wx1 : wx0;

    float w00 = wx * wy0 * wz0;
    float w01 = wx * wy0 * wz1;
    float w10 = wx * wy1 * wz0;
    float w11 = wx * wy1 * wz1;

    float4 acc;
    {
        float2 f0 = __half22float2(*(__half2*)&r00.x);
        float2 f1 = __half22float2(*(__half2*)&r00.y);
        acc.x = f0.x * w00;  acc.y = f0.y * w00;
        acc.z = f1.x * w00;  acc.w = f1.y * w00;
    }
    {
        float2 f0 = __half22float2(*(__half2*)&r01.x);
        float2 f1 = __half22float2(*(__half2*)&r01.y);
        acc.x = fmaf(f0.x, w01, acc.x);  acc.y = fmaf(f0.y, w01, acc.y);
        acc.z = fmaf(f1.x, w01, acc.z);  acc.w = fmaf(f1.y, w01, acc.w);
    }
    {
        float2 f0 = __half22float2(*(__half2*)&r10.x);
        float2 f1 = __half22float2(*(__half2*)&r10.y);
        acc.x = fmaf(f0.x, w10, acc.x);  acc.y = fmaf(f0.y, w10, acc.y);
        acc.z = fmaf(f1.x, w10, acc.z);  acc.w = fmaf(f1.y, w10, acc.w);
    }
    {
        float2 f0 = __half22float2(*(__half2*)&r11.x);
        float2 f1 = __half22float2(*(__half2*)&r11.y);
        acc.x = fmaf(f0.x, w11, acc.x);  acc.y = fmaf(f0.y, w11, acc.y);
        acc.z = fmaf(f1.x, w11, acc.z);  acc.w = fmaf(f1.y, w11, acc.w);
    }

    // Pair reduction: lane 2i += lane 2i+1.
    acc.x += __shfl_xor_sync(0xffffffffu, acc.x, 1);
    acc.y += __shfl_xor_sync(0xffffffffu, acc.y, 1);
    acc.z += __shfl_xor_sync(0xffffffffu, acc.z, 1);
    acc.w += __shfl_xor_sync(0xffffffffu, acc.w, 1);
    return acc;
}

__global__ __launch_bounds__(TPB, 4) void hashed_interp_kernel(
    const float* __restrict__ pos,
    float4* __restrict__ out,
    int batch)
{
    __shared__ float sp[3 * PPB];

    int t = threadIdx.x;
    int base = blockIdx.x * PPB;

    // Stage this block's positions (3*512 floats = 384 float4s) coalesced.
    {
        int nfloats = 3 * (batch - base);
        if (nfloats > 3 * PPB) nfloats = 3 * PPB;
        const float4* src = (const float4*)(pos + 3 * base);  // 6144B-aligned
        int nvec = nfloats >> 2;
        for (int v = t; v < nvec; v += TPB) ((float4*)sp)[v] = src[v];
        int rem = nfloats & 3;
        if (t < rem) sp[(nvec << 2) + t] = pos[3 * base + (nvec << 2) + t];
    }
    __syncthreads();

    int slot = t >> 1;          // 0..127
    int xbit = t & 1;
    int iA = base + slot;
    int iB = iA + HALF;
    int iC = iB + HALF;
    int iD = iC + HALF;
    bool hasA = iA < batch;
    bool hasB = iB < batch;
    bool hasC = iC < batch;
    bool hasD = iD < batch;

    const uint2* tb2 = (const uint2*)g_tbl16;   // one uint2 = one 8B row

    uint2 rA00, rA01, rA10, rA11;
    uint2 rB00, rB01, rB10, rB11;
    uint2 rC00, rC01, rC10, rC11;
    uint2 rD00, rD01, rD10, rD11;

    // Phase the hash computation so only 4 index regs are live at a time;
    // all 16 loads end up in flight before any weight math.
    {
        unsigned h0, h1, h2, h3;
        hash4(sp, slot, xbit, h0, h1, h2, h3);
        if (hasA) {
            rA00 = __ldg(&tb2[h0]);
            rA01 = __ldg(&tb2[h1]);
            rA10 = __ldg(&tb2[h2]);
            rA11 = __ldg(&tb2[h3]);
        }
    }
    {
        unsigned h0, h1, h2, h3;
        hash4(sp, slot + HALF, xbit, h0, h1, h2, h3);
        if (hasB) {
            rB00 = __ldg(&tb2[h0]);
            rB01 = __ldg(&tb2[h1]);
            rB10 = __ldg(&tb2[h2]);
            rB11 = __ldg(&tb2[h3]);
        }
    }
    {
        unsigned h0, h1, h2, h3;
        hash4(sp, slot + 2 * HALF, xbit, h0, h1, h2, h3);
        if (hasC) {
            rC00 = __ldg(&tb2[h0]);
            rC01 = __ldg(&tb2[h1]);
            rC10 = __ldg(&tb2[h2]);
            rC11 = __ldg(&tb2[h3]);
        }
    }
    {
        unsigned h0, h1, h2, h3;
        hash4(sp, slot + 3 * HALF, xbit, h0, h1, h2, h3);
        if (hasD) {
            rD00 = __ldg(&tb2[h0]);
            rD01 = __ldg(&tb2[h1]);
            rD10 = __ldg(&tb2[h2]);
            rD11 = __ldg(&tb2[h3]);
        }
    }

    if (hasA) {
        float4 acc = interp_point(sp, slot, xbit, rA00, rA01, rA10, rA11);
        if (xbit == 0) __stcs(&out[iA], acc);
    }
    if (hasB) {
        float4 acc = interp_point(sp, slot + HALF, xbit, rB00, rB01, rB10, rB11);
        if (xbit == 0) __stcs(&out[iB], acc);
    }
    if (hasC) {
        float4 acc = interp_point(sp, slot + 2 * HALF, xbit, rC00, rC01, rC10, rC11);
        if (xbit == 0) __stcs(&out[iC], acc);
    }
    if (hasD) {
        float4 acc = interp_point(sp, slot + 3 * HALF, xbit, rD00, rD01, rD10, rD11);
        if (xbit == 0) __stcs(&out[iD], acc);
    }
}

extern "C" void kernel_launch(void* const* d_in, const int* in_sizes, int n_in,
                              void* d_out, int out_size)
{
    const float* pos = (const float*)d_in[0];
    const float4* table = (const float4*)d_in[1];
    float4* out = (float4*)d_out;
    int batch = in_sizes[0] / 3;

    // Prepass: f32 table -> fp16 shadow (4MB), 2 rows/thread, STG.128.
    convert_table_kernel<<<(HG_ENTRIES / 2 + 255) / 256, 256>>>(table);

    int blocks = (batch + PPB - 1) / PPB;
    hashed_interp_kernel<<<blocks, TPB>>>(pos, out, batch);
}